// round 10
// baseline (speedup 1.0000x reference)
#include <cuda_runtime.h>

#define N197   197
#define NN     38809        // 197*197
#define NNP    38812        // padded stride (float4-aligned)
#define NBATCH 32
#define NLAY   2            // processed layers: 4 and 11
#define KDISC  9702         // int(197*197*0.25)
#define PADR   256
#define PADC   208
#define NTF    1024

__device__ float    g_attn[NLAY * NBATCH * NNP];
__device__ float    g_norm[NLAY * NBATCH * PADR * PADC];   // zero-init; rows>=197 never written
__device__ unsigned g_hist[NLAY * NBATCH * 4096];          // zero-init; fused re-zeroes after use

// ---------------------------------------------------------------------------
// 1) mean over heads + round-0 histogram: one element per thread, no loop,
//    warp-aggregated global atomics (no smem hist, no merge pass)
// ---------------------------------------------------------------------------
__global__ void __launch_bounds__(256) mean_kernel(const float* __restrict__ in) {
    const int lb = blockIdx.y;           // 0..63 = li*32 + b
    const int li = lb >> 5, b = lb & 31;
    const int layer = li ? 11 : 4;
    const float* __restrict__ base = in + ((long)(layer * NBATCH + b) * 12) * NN;
    const int lane = threadIdx.x & 31;

    int p = blockIdx.x * 256 + threadIdx.x;
    bool valid = p < NN;
    float s = 0.f;
    if (valid) {
#pragma unroll
        for (int h = 0; h < 12; h++) s += __ldg(&base[(long)h * NN + p]);
        s *= (1.0f / 12.0f);
        g_attn[(long)lb * NNP + p] = s;
    }
    unsigned key = __float_as_uint(s) >> 20;
    unsigned m = __ballot_sync(0xffffffffu, valid);
    if (valid) {
        unsigned grp = __match_any_sync(m, key);
        if (lane == (int)__ffs(grp) - 1)
            atomicAdd(&g_hist[lb * 4096 + key], __popc(grp));
    }
}

// ---------------------------------------------------------------------------
// block-wide "pick the bucket containing rank"
// s_out: [0]=chosen bucket, [1]=rank within bucket, [2]=count below
// ---------------------------------------------------------------------------
template<int PER>
__device__ __forceinline__ void block_pick(const unsigned* cnts, int nb, int rank,
                                           unsigned* wtot, int* s_out) {
    const int t = threadIdx.x, lane = t & 31, wid = t >> 5;
    const int base = t * PER;
    unsigned h[PER];
    unsigned sum = 0;
    if (base < nb) {
#pragma unroll
        for (int j = 0; j < PER; j++) { h[j] = cnts[base + j]; sum += h[j]; }
    }
    unsigned x = sum;
#pragma unroll
    for (int o = 1; o < 32; o <<= 1) {
        unsigned y = __shfl_up_sync(0xffffffffu, x, o);
        if (lane >= o) x += y;
    }
    if (lane == 31) wtot[wid] = x;
    __syncthreads();
    if (wid == 0) {
        unsigned y = wtot[lane];
#pragma unroll
        for (int o = 1; o < 32; o <<= 1) {
            unsigned z = __shfl_up_sync(0xffffffffu, y, o);
            if (lane >= o) y += z;
        }
        wtot[lane] = y;
    }
    __syncthreads();
    unsigned excl = x - sum + (wid ? wtot[wid - 1] : 0u);
    if (base < nb && (unsigned)rank >= excl && (unsigned)rank < excl + sum) {
        unsigned c = excl; int ch = base;
#pragma unroll
        for (int j = 0; j < PER; j++) {
            if (c + h[j] > (unsigned)rank) { ch = base + j; break; }
            c += h[j];
        }
        s_out[0] = ch; s_out[1] = rank - (int)c; s_out[2] = (int)c;
    }
    __syncthreads();
}

// ---------------------------------------------------------------------------
// 2) fused: pick0 -> load(L2)+hist1 -> pick1 -> [rare round-2/ties]
//    -> single row sweep: discard + rowsum + normalized write (rows < 197)
// ---------------------------------------------------------------------------
__global__ void __launch_bounds__(NTF) fused_kernel() {
    extern __shared__ float sm[];          // NN floats
    __shared__ unsigned hist[4096];
    __shared__ unsigned wtot[32];
    __shared__ int s_pick[3];

    const int lb = blockIdx.x;
    const int t = threadIdx.x, lane = t & 31, wid = t >> 5;

    block_pick<4>(&g_hist[lb * 4096], 4096, KDISC - 1, wtot, s_pick);
    const int B1 = s_pick[0];
    int rank = s_pick[1];

    for (int i = t; i < 4096; i += NTF) { hist[i] = 0u; g_hist[lb * 4096 + i] = 0u; }
    __syncthreads();

    const float* src = g_attn + (long)lb * NNP;
    const float4* s4 = (const float4*)src;
    float4* d4 = (float4*)sm;
    const int N4 = NN / 4;                 // 9702
    const int IT4 = (N4 + NTF - 1) / NTF;  // 10
    for (int k = 0; k < IT4; k++) {
        int i = k * NTF + t;
        if (i < N4) {
            float4 a = s4[i];
            d4[i] = a;
            const float vv[4] = {a.x, a.y, a.z, a.w};
#pragma unroll
            for (int j = 0; j < 4; j++) {
                unsigned key = __float_as_uint(vv[j]);
                if ((int)(key >> 20) == B1) atomicAdd(&hist[(key >> 8) & 0xFFFu], 1u);
            }
        }
    }
    if (t == 0) {                          // tail element 38808
        float v = src[NN - 1]; sm[NN - 1] = v;
        unsigned key = __float_as_uint(v);
        if ((int)(key >> 20) == B1) atomicAdd(&hist[(key >> 8) & 0xFFFu], 1u);
    }
    __syncthreads();

    block_pick<4>(hist, 4096, rank, wtot, s_pick);
    const int B2 = s_pick[0];
    rank = s_pick[1];
    const unsigned K24 = ((unsigned)B1 << 12) | (unsigned)B2;
    const unsigned ties2 = hist[B2];

    int mode;           // 0: zero key24<=K24 | 1: zero key<=T | 2: zero key<T (ties pre-zeroed)
    unsigned T = 0;
    if (ties2 == 1u) {
        mode = 0;
    } else {
        for (int i = t; i < 256; i += NTF) hist[i] = 0u;
        __syncthreads();
        const int IT = (NN + NTF - 1) / NTF;   // 38
        for (int k = 0; k < IT; k++) {
            int i = k * NTF + t;
            if (i < NN) {
                unsigned key = __float_as_uint(sm[i]);
                if ((key >> 8) == K24) atomicAdd(&hist[key & 0xFFu], 1u);
            }
        }
        __syncthreads();
        block_pick<1>(hist, 256, rank, wtot, s_pick);
        const int B3 = s_pick[0];
        const int rank3 = s_pick[1];
        T = (K24 << 8) | (unsigned)B3;
        const unsigned ties3 = hist[B3];
        const int need = rank3 + 1;
        if ((unsigned)need == ties3) {
            mode = 1;
        } else {
            mode = 2;
            const int SEG = (NN + NTF - 1) / NTF;
            int start = t * SEG, end = min(start + SEG, NN);
            int cnt = 0;
            for (int i = start; i < end; i++)
                if (__float_as_uint(sm[i]) == T) cnt++;
            int x = cnt;
#pragma unroll
            for (int o = 1; o < 32; o <<= 1) {
                int y = __shfl_up_sync(0xffffffffu, x, o);
                if (lane >= o) x += y;
            }
            if (lane == 31) wtot[wid] = (unsigned)x;
            __syncthreads();
            if (wid == 0) {
                unsigned y = wtot[lane];
#pragma unroll
                for (int o = 1; o < 32; o <<= 1) {
                    unsigned z = __shfl_up_sync(0xffffffffu, y, o);
                    if (lane >= o) y += z;
                }
                wtot[lane] = y;
            }
            __syncthreads();
            int pre = x - cnt + (wid ? (int)wtot[wid - 1] : 0);
            for (int i = start; i < end; i++) {
                if (__float_as_uint(sm[i]) == T) {
                    if (pre < need && i != 0) sm[i] = 0.f;
                    pre++;
                }
            }
            __syncthreads();
        }
    }

    // ---- single sweep: discard + row sum + normalized write (warp per row) ----
    for (int r = wid; r < N197; r += 32) {
        const int rowbase = r * N197;
        float s = 0.f;
        for (int c = lane; c < N197; c += 32) {
            int i = rowbase + c;
            float v = sm[i];
            unsigned key = __float_as_uint(v);
            bool z = (mode == 0) ? ((key >> 8) <= K24)
                   : (mode == 1) ? (key <= T)
                                 : (key < T);
            if (z && i != 0) { sm[i] = 0.f; v = 0.f; }
            s += v;
        }
#pragma unroll
        for (int o = 16; o; o >>= 1) s += __shfl_xor_sync(0xffffffffu, s, o);
        const float inv = 1.0f / (s + 1.0f);   // the *0.5 cancels: (x+d)/(sum+1)

        float4* orow = (float4*)(g_norm + (long)lb * (PADR * PADC) + r * PADC);
        for (int v4 = lane; v4 < PADC / 4; v4 += 32) {   // 52 float4 per row
            int c0 = v4 * 4;
            float4 val;
            val.x = (c0     < N197) ? (sm[rowbase + c0    ] + (r == c0     ? 1.f : 0.f)) * inv : 0.f;
            val.y = (c0 + 1 < N197) ? (sm[rowbase + c0 + 1] + (r == c0 + 1 ? 1.f : 0.f)) * inv : 0.f;
            val.z = (c0 + 2 < N197) ? (sm[rowbase + c0 + 2] + (r == c0 + 2 ? 1.f : 0.f)) * inv : 0.f;
            val.w = (c0 + 3 < N197) ? (sm[rowbase + c0 + 3] + (r == c0 + 3 ? 1.f : 0.f)) * inv : 0.f;
            orow[v4] = val;
        }
    }
}

// ---------------------------------------------------------------------------
// 3) out[b] = A11[b] @ A4[b]: 128x128 tile, 256 threads, 8x8 microtile,
//    m-paired f32x2, conflict-free padded B groups, double-buffered smem.
// ---------------------------------------------------------------------------
#define BM 128
#define BN 128
#define BK 16
#define ASTR 132        // As row stride in floats (16B multiple)
#define BROW 192        // Bs row: 16 groups * 12 floats (8 data + 4 pad)

#define FMAF2(d, a, bb) \
    asm("fma.rn.f32x2 %0, %1, %2, %0;" : "+l"(d) : "l"(a), "l"(bb))
#define SPLAT2(d, v) \
    asm("mov.b64 %0, {%1, %1};" : "=l"(d) : "r"(__float_as_uint(v)))

__global__ void __launch_bounds__(256) gemm_kernel(float* __restrict__ C) {
    const int b = blockIdx.z;
    const float* __restrict__ A  = g_norm + (long)(NBATCH + b) * (PADR * PADC); // layer 11
    const float* __restrict__ Bm = g_norm + (long)b * (PADR * PADC);            // layer 4
    C += (long)b * NN;

    __shared__ float As[2][BK][ASTR];      // transposed: As[k][m]  (2 x 8.4 KB)
    __shared__ float Bs[2][BK * BROW];     // padded groups         (2 x 12.3 KB)

    const int t  = threadIdx.x;        // 0..255
    const int tx = t & 15;             // n-group: 8 cols
    const int ty = t >> 4;             // m-group: 8 rows
    const int row0 = blockIdx.y * BM, col0 = blockIdx.x * BN;

    unsigned long long acc[4][8];      // [m-pair][n]
#pragma unroll
    for (int mp = 0; mp < 4; mp++)
#pragma unroll
        for (int n = 0; n < 8; n++) acc[mp][n] = 0ull;

    // loader indices: 512 float4 per tile per operand; 2 per thread
    const int aq0 = t >> 7,      ar0 = t & 127;
    const int aq1 = (t + 256) >> 7, ar1 = t & 127;   // idx+256: same ar, aq+2
    const int bk0 = t >> 5,      cq0 = t & 31;
    const int bk1 = (t + 256) >> 5, cq1 = t & 31;    // bk+8, same cq

    float4 pa[2], pb[2];
    pa[0] = *(const float4*)&A[(row0 + ar0) * PADC + aq0 * 4];
    pa[1] = *(const float4*)&A[(row0 + ar1) * PADC + aq1 * 4];
    pb[0] = *(const float4*)&Bm[bk0 * PADC + col0 + cq0 * 4];
    pb[1] = *(const float4*)&Bm[bk1 * PADC + col0 + cq1 * 4];

    // store tile 0 into buffer 0
    {
        As[0][aq0 * 4 + 0][ar0] = pa[0].x; As[0][aq0 * 4 + 1][ar0] = pa[0].y;
        As[0][aq0 * 4 + 2][ar0] = pa[0].z; As[0][aq0 * 4 + 3][ar0] = pa[0].w;
        As[0][aq1 * 4 + 0][ar1] = pa[1].x; As[0][aq1 * 4 + 1][ar1] = pa[1].y;
        As[0][aq1 * 4 + 2][ar1] = pa[1].z; As[0][aq1 * 4 + 3][ar1] = pa[1].w;
        int g0 = cq0 >> 1, w0 = cq0 & 1;
        *(float4*)&Bs[0][bk0 * BROW + g0 * 12 + w0 * 4] = pb[0];
        *(float4*)&Bs[0][bk1 * BROW + g0 * 12 + w0 * 4] = pb[1];
    }
    __syncthreads();

    const int NKT = PADC / BK;             // 13
    for (int kt = 0; kt < NKT; kt++) {
        const int buf = kt & 1;
        if (kt + 1 < NKT) {                // prefetch next tile into regs
            int k0 = (kt + 1) * BK;
            pa[0] = *(const float4*)&A[(row0 + ar0) * PADC + k0 + aq0 * 4];
            pa[1] = *(const float4*)&A[(row0 + ar1) * PADC + k0 + aq1 * 4];
            pb[0] = *(const float4*)&Bm[(k0 + bk0) * PADC + col0 + cq0 * 4];
            pb[1] = *(const float4*)&Bm[(k0 + bk1) * PADC + col0 + cq1 * 4];
        }

#pragma unroll
        for (int kk = 0; kk < BK; kk++) {
            ulonglong2 a01 = *(const ulonglong2*)&As[buf][kk][ty * 8];
            ulonglong2 a23 = *(const ulonglong2*)&As[buf][kk][ty * 8 + 4];
            const float* bg = &Bs[buf][kk * BROW + tx * 12];
            float4 b0 = *(const float4*)bg;
            {
                unsigned long long s0, s1, s2, s3;
                SPLAT2(s0, b0.x); SPLAT2(s1, b0.y); SPLAT2(s2, b0.z); SPLAT2(s3, b0.w);
                FMAF2(acc[0][0], a01.x, s0); FMAF2(acc[1][0], a01.y, s0);
                FMAF2(acc[2][0], a23.x, s0); FMAF2(acc[3][0], a23.y, s0);
                FMAF2(acc[0][1], a01.x, s1); FMAF2(acc[1][1], a01.y, s1);
                FMAF2(acc[2][1], a23.x, s1); FMAF2(acc[3][1], a23.y, s1);
                FMAF2(acc[0][2], a01.x, s2); FMAF2(acc[1][2], a01.y, s2);
                FMAF2(acc[2][2], a23.x, s2); FMAF2(acc[3][2], a23.y, s2);
                FMAF2(acc[0][3], a01.x, s3); FMAF2(acc[1][3], a01.y, s3);
                FMAF2(acc[2][3], a23.x, s3); FMAF2(acc[3][3], a23.y, s3);
            }
            float4 b1 = *(const float4*)(bg + 4);
            {
                unsigned long long s0, s1, s2, s3;
                SPLAT2(s0, b1.x); SPLAT2(s1, b1.y); SPLAT2(s2, b1.z); SPLAT2(s3, b1.w);
                FMAF2(acc[0][4], a01.x, s0); FMAF2(acc[1][4], a01.y, s0);
                FMAF2(acc[2][4], a23.x, s0); FMAF2(acc[3][4], a23.y, s0);
                FMAF2(acc[0][5], a01.x, s1); FMAF2(acc[1][5], a01.y, s1);
                FMAF2(acc[2][5], a23.x, s1); FMAF2(acc[3][5], a23.y, s1);
                FMAF2(acc[0][6], a01.x, s2); FMAF2(acc[1][6], a01.y, s2);
                FMAF2(acc[2][6], a23.x, s2); FMAF2(acc[3][6], a23.y, s2);
                FMAF2(acc[0][7], a01.x, s3); FMAF2(acc[1][7], a01.y, s3);
                FMAF2(acc[2][7], a23.x, s3); FMAF2(acc[3][7], a23.y, s3);
            }
        }

        if (kt + 1 < NKT) {                // store next tile into other buffer
            const int nb = buf ^ 1;
            As[nb][aq0 * 4 + 0][ar0] = pa[0].x; As[nb][aq0 * 4 + 1][ar0] = pa[0].y;
            As[nb][aq0 * 4 + 2][ar0] = pa[0].z; As[nb][aq0 * 4 + 3][ar0] = pa[0].w;
            As[nb][aq1 * 4 + 0][ar1] = pa[1].x; As[nb][aq1 * 4 + 1][ar1] = pa[1].y;
            As[nb][aq1 * 4 + 2][ar1] = pa[1].z; As[nb][aq1 * 4 + 3][ar1] = pa[1].w;
            int g0 = cq0 >> 1, w0 = cq0 & 1;
            *(float4*)&Bs[nb][bk0 * BROW + g0 * 12 + w0 * 4] = pb[0];
            *(float4*)&Bs[nb][bk1 * BROW + g0 * 12 + w0 * 4] = pb[1];
            __syncthreads();
        }
    }

#pragma unroll
    for (int mp = 0; mp < 4; mp++) {
#pragma unroll
        for (int n = 0; n < 8; n++) {
            unsigned ulo, uhi;
            asm("mov.b64 {%0, %1}, %2;" : "=r"(ulo), "=r"(uhi) : "l"(acc[mp][n]));
            int gr = row0 + ty * 8 + mp * 2;
            int gc = col0 + tx * 8 + n;
            if (gc < N197) {
                if (gr < N197)     C[gr * N197 + gc]       = __uint_as_float(ulo);
                if (gr + 1 < N197) C[(gr + 1) * N197 + gc] = __uint_as_float(uhi);
            }
        }
    }
}

// ---------------------------------------------------------------------------
extern "C" void kernel_launch(void* const* d_in, const int* in_sizes, int n_in,
                              void* d_out, int out_size) {
    const float* attn = (const float*)d_in[0];  // (12,32,12,197,197) fp32
    float* out = (float*)d_out;                 // (32,197,197) fp32
    (void)in_sizes; (void)n_in; (void)out_size;

    cudaFuncSetAttribute(fused_kernel, cudaFuncAttributeMaxDynamicSharedMemorySize,
                         NN * (int)sizeof(float));

    dim3 gm(152, NLAY * NBATCH);    // 152*256 = 38912 >= NN, one element/thread
    mean_kernel<<<gm, 256>>>(attn);
    fused_kernel<<<NLAY * NBATCH, NTF, NN * sizeof(float)>>>();
    dim3 gg((N197 + BN - 1) / BN, (N197 + BM - 1) / BM, NBATCH);
    gemm_kernel<<<gg, 256>>>(out);
}

// round 11
// speedup vs baseline: 1.0887x; 1.0887x over previous
#include <cuda_runtime.h>

#define N197   197
#define NN     38809        // 197*197
#define NNP    38812        // padded stride (float4-aligned)
#define NBATCH 32
#define NLAY   2            // processed layers: 4 and 11
#define KDISC  9702         // int(197*197*0.25)
#define PADR   256
#define PADC   208
#define NTF    1024

__device__ float    g_attn[NLAY * NBATCH * NNP];
__device__ float    g_norm[NLAY * NBATCH * PADR * PADC];   // zero-init; rows>=197 never written
__device__ unsigned g_hist[NLAY * NBATCH * 4096];          // zero-init; fused re-zeroes after use

// ---------------------------------------------------------------------------
// 1) mean over heads + round-0 histogram. __ldcs streaming reads (don't pollute
//    L2 — keep g_attn resident for fused). 2 elements/thread for MLP + less churn.
// ---------------------------------------------------------------------------
__global__ void __launch_bounds__(256) mean_kernel(const float* __restrict__ in) {
    const int lb = blockIdx.y;           // 0..63 = li*32 + b
    const int li = lb >> 5, b = lb & 31;
    const int layer = li ? 11 : 4;
    const float* __restrict__ base = in + ((long)(layer * NBATCH + b) * 12) * NN;
    const int lane = threadIdx.x & 31;

    const int p0 = blockIdx.x * 512 + threadIdx.x;
    const int p1 = p0 + 256;
    const bool v0 = p0 < NN, v1 = p1 < NN;
    float s0 = 0.f, s1 = 0.f;
    if (v0) {
#pragma unroll
        for (int h = 0; h < 12; h++) s0 += __ldcs(&base[(long)h * NN + p0]);
    }
    if (v1) {
#pragma unroll
        for (int h = 0; h < 12; h++) s1 += __ldcs(&base[(long)h * NN + p1]);
    }
    s0 *= (1.0f / 12.0f);
    s1 *= (1.0f / 12.0f);
    if (v0) g_attn[(long)lb * NNP + p0] = s0;
    if (v1) g_attn[(long)lb * NNP + p1] = s1;

    unsigned* hb = &g_hist[lb * 4096];
    {
        unsigned key = __float_as_uint(s0) >> 20;
        unsigned m = __ballot_sync(0xffffffffu, v0);
        if (v0) {
            unsigned grp = __match_any_sync(m, key);
            if (lane == (int)__ffs(grp) - 1) atomicAdd(&hb[key], __popc(grp));
        }
    }
    {
        unsigned key = __float_as_uint(s1) >> 20;
        unsigned m = __ballot_sync(0xffffffffu, v1);
        if (v1) {
            unsigned grp = __match_any_sync(m, key);
            if (lane == (int)__ffs(grp) - 1) atomicAdd(&hb[key], __popc(grp));
        }
    }
}

// ---------------------------------------------------------------------------
// block-wide "pick the bucket containing rank"
// s_out: [0]=chosen bucket, [1]=rank within bucket, [2]=count below
// ---------------------------------------------------------------------------
template<int PER>
__device__ __forceinline__ void block_pick(const unsigned* cnts, int nb, int rank,
                                           unsigned* wtot, int* s_out) {
    const int t = threadIdx.x, lane = t & 31, wid = t >> 5;
    const int base = t * PER;
    unsigned h[PER];
    unsigned sum = 0;
    if (base < nb) {
#pragma unroll
        for (int j = 0; j < PER; j++) { h[j] = cnts[base + j]; sum += h[j]; }
    }
    unsigned x = sum;
#pragma unroll
    for (int o = 1; o < 32; o <<= 1) {
        unsigned y = __shfl_up_sync(0xffffffffu, x, o);
        if (lane >= o) x += y;
    }
    if (lane == 31) wtot[wid] = x;
    __syncthreads();
    if (wid == 0) {
        unsigned y = wtot[lane];
#pragma unroll
        for (int o = 1; o < 32; o <<= 1) {
            unsigned z = __shfl_up_sync(0xffffffffu, y, o);
            if (lane >= o) y += z;
        }
        wtot[lane] = y;
    }
    __syncthreads();
    unsigned excl = x - sum + (wid ? wtot[wid - 1] : 0u);
    if (base < nb && (unsigned)rank >= excl && (unsigned)rank < excl + sum) {
        unsigned c = excl; int ch = base;
#pragma unroll
        for (int j = 0; j < PER; j++) {
            if (c + h[j] > (unsigned)rank) { ch = base + j; break; }
            c += h[j];
        }
        s_out[0] = ch; s_out[1] = rank - (int)c; s_out[2] = (int)c;
    }
    __syncthreads();
}

// ---------------------------------------------------------------------------
// 2) fused: pick0 -> reg-staged load + hist1 -> pick1 -> [rare round-2/ties]
//    -> single row sweep: discard + rowsum + normalized write
// ---------------------------------------------------------------------------
__global__ void __launch_bounds__(NTF) fused_kernel() {
    extern __shared__ float sm[];          // NN floats
    __shared__ unsigned hist[4096];
    __shared__ unsigned wtot[32];
    __shared__ int s_pick[3];

    const int lb = blockIdx.x;
    const int t = threadIdx.x, lane = t & 31, wid = t >> 5;

    block_pick<4>(&g_hist[lb * 4096], 4096, KDISC - 1, wtot, s_pick);
    const int B1 = s_pick[0];
    int rank = s_pick[1];

    for (int i = t; i < 4096; i += NTF) { hist[i] = 0u; g_hist[lb * 4096 + i] = 0u; }
    __syncthreads();

    // ---- register-staged load (batches of 5 float4, MLP=5/thread) + hist1 ----
    const float* src = g_attn + (long)lb * NNP;
    const float4* s4 = (const float4*)src;
    float4* d4 = (float4*)sm;
    const int N4 = NN / 4;                 // 9702
    {
        float4 v[5];
#pragma unroll
        for (int k = 0; k < 5; k++) v[k] = s4[k * NTF + t];      // max 5119 < 9702
#pragma unroll
        for (int k = 0; k < 5; k++) {
            int i = k * NTF + t;
            d4[i] = v[k];
            const float vv[4] = {v[k].x, v[k].y, v[k].z, v[k].w};
#pragma unroll
            for (int j = 0; j < 4; j++) {
                unsigned key = __float_as_uint(vv[j]);
                if ((int)(key >> 20) == B1) atomicAdd(&hist[(key >> 8) & 0xFFFu], 1u);
            }
        }
        bool ok[5];
#pragma unroll
        for (int k = 0; k < 5; k++) {
            int i = (k + 5) * NTF + t;
            ok[k] = i < N4;
            v[k] = ok[k] ? s4[i] : make_float4(0.f, 0.f, 0.f, 0.f);
        }
#pragma unroll
        for (int k = 0; k < 5; k++) {
            if (ok[k]) {
                int i = (k + 5) * NTF + t;
                d4[i] = v[k];
                const float vv[4] = {v[k].x, v[k].y, v[k].z, v[k].w};
#pragma unroll
                for (int j = 0; j < 4; j++) {
                    unsigned key = __float_as_uint(vv[j]);
                    if ((int)(key >> 20) == B1) atomicAdd(&hist[(key >> 8) & 0xFFFu], 1u);
                }
            }
        }
    }
    if (t == 0) {                          // tail element 38808
        float v = src[NN - 1]; sm[NN - 1] = v;
        unsigned key = __float_as_uint(v);
        if ((int)(key >> 20) == B1) atomicAdd(&hist[(key >> 8) & 0xFFFu], 1u);
    }
    __syncthreads();

    block_pick<4>(hist, 4096, rank, wtot, s_pick);
    const int B2 = s_pick[0];
    rank = s_pick[1];
    const unsigned K24 = ((unsigned)B1 << 12) | (unsigned)B2;
    const unsigned ties2 = hist[B2];

    int mode;           // 0: zero key24<=K24 | 1: zero key<=T | 2: zero key<T (ties pre-zeroed)
    unsigned T = 0;
    if (ties2 == 1u) {
        mode = 0;
    } else {
        for (int i = t; i < 256; i += NTF) hist[i] = 0u;
        __syncthreads();
        const int IT = (NN + NTF - 1) / NTF;   // 38
        for (int k = 0; k < IT; k++) {
            int i = k * NTF + t;
            if (i < NN) {
                unsigned key = __float_as_uint(sm[i]);
                if ((key >> 8) == K24) atomicAdd(&hist[key & 0xFFu], 1u);
            }
        }
        __syncthreads();
        block_pick<1>(hist, 256, rank, wtot, s_pick);
        const int B3 = s_pick[0];
        const int rank3 = s_pick[1];
        T = (K24 << 8) | (unsigned)B3;
        const unsigned ties3 = hist[B3];
        const int need = rank3 + 1;
        if ((unsigned)need == ties3) {
            mode = 1;
        } else {
            mode = 2;
            const int SEG = (NN + NTF - 1) / NTF;
            int start = t * SEG, end = min(start + SEG, NN);
            int cnt = 0;
            for (int i = start; i < end; i++)
                if (__float_as_uint(sm[i]) == T) cnt++;
            int x = cnt;
#pragma unroll
            for (int o = 1; o < 32; o <<= 1) {
                int y = __shfl_up_sync(0xffffffffu, x, o);
                if (lane >= o) x += y;
            }
            if (lane == 31) wtot[wid] = (unsigned)x;
            __syncthreads();
            if (wid == 0) {
                unsigned y = wtot[lane];
#pragma unroll
                for (int o = 1; o < 32; o <<= 1) {
                    unsigned z = __shfl_up_sync(0xffffffffu, y, o);
                    if (lane >= o) y += z;
                }
                wtot[lane] = y;
            }
            __syncthreads();
            int pre = x - cnt + (wid ? (int)wtot[wid - 1] : 0);
            for (int i = start; i < end; i++) {
                if (__float_as_uint(sm[i]) == T) {
                    if (pre < need && i != 0) sm[i] = 0.f;
                    pre++;
                }
            }
            __syncthreads();
        }
    }

    // ---- single sweep: discard + row sum + normalized write (warp per row) ----
    for (int r = wid; r < N197; r += 32) {
        const int rowbase = r * N197;
        float s = 0.f;
        for (int c = lane; c < N197; c += 32) {
            int i = rowbase + c;
            float v = sm[i];
            unsigned key = __float_as_uint(v);
            bool z = (mode == 0) ? ((key >> 8) <= K24)
                   : (mode == 1) ? (key <= T)
                                 : (key < T);
            if (z && i != 0) { sm[i] = 0.f; v = 0.f; }
            s += v;
        }
#pragma unroll
        for (int o = 16; o; o >>= 1) s += __shfl_xor_sync(0xffffffffu, s, o);
        const float inv = 1.0f / (s + 1.0f);   // the *0.5 cancels: (x+d)/(sum+1)

        float4* orow = (float4*)(g_norm + (long)lb * (PADR * PADC) + r * PADC);
        for (int v4 = lane; v4 < PADC / 4; v4 += 32) {   // 52 float4 per row
            int c0 = v4 * 4;
            float4 val;
            val.x = (c0     < N197) ? (sm[rowbase + c0    ] + (r == c0     ? 1.f : 0.f)) * inv : 0.f;
            val.y = (c0 + 1 < N197) ? (sm[rowbase + c0 + 1] + (r == c0 + 1 ? 1.f : 0.f)) * inv : 0.f;
            val.z = (c0 + 2 < N197) ? (sm[rowbase + c0 + 2] + (r == c0 + 2 ? 1.f : 0.f)) * inv : 0.f;
            val.w = (c0 + 3 < N197) ? (sm[rowbase + c0 + 3] + (r == c0 + 3 ? 1.f : 0.f)) * inv : 0.f;
            orow[v4] = val;
        }
    }
}

// ---------------------------------------------------------------------------
// 3) out[b] = A11[b] @ A4[b]: 128x128 tile, 256 threads, 8x8 microtile,
//    m-paired f32x2, conflict-free padded B groups, double-buffered smem.
// ---------------------------------------------------------------------------
#define BM 128
#define BN 128
#define BK 16
#define ASTR 132        // As row stride in floats (16B multiple)
#define BROW 192        // Bs row: 16 groups * 12 floats (8 data + 4 pad)

#define FMAF2(d, a, bb) \
    asm("fma.rn.f32x2 %0, %1, %2, %0;" : "+l"(d) : "l"(a), "l"(bb))
#define SPLAT2(d, v) \
    asm("mov.b64 %0, {%1, %1};" : "=l"(d) : "r"(__float_as_uint(v)))

__global__ void __launch_bounds__(256) gemm_kernel(float* __restrict__ C) {
    const int b = blockIdx.z;
    const float* __restrict__ A  = g_norm + (long)(NBATCH + b) * (PADR * PADC); // layer 11
    const float* __restrict__ Bm = g_norm + (long)b * (PADR * PADC);            // layer 4
    C += (long)b * NN;

    __shared__ float As[2][BK][ASTR];      // transposed: As[k][m]
    __shared__ float Bs[2][BK * BROW];     // padded groups

    const int t  = threadIdx.x;        // 0..255
    const int tx = t & 15;             // n-group: 8 cols
    const int ty = t >> 4;             // m-group: 8 rows
    const int row0 = blockIdx.y * BM, col0 = blockIdx.x * BN;

    unsigned long long acc[4][8];      // [m-pair][n]
#pragma unroll
    for (int mp = 0; mp < 4; mp++)
#pragma unroll
        for (int n = 0; n < 8; n++) acc[mp][n] = 0ull;

    const int aq0 = t >> 7,         ar0 = t & 127;
    const int aq1 = (t + 256) >> 7, ar1 = t & 127;
    const int bk0 = t >> 5,         cq0 = t & 31;
    const int bk1 = (t + 256) >> 5, cq1 = t & 31;

    float4 pa[2], pb[2];
    pa[0] = *(const float4*)&A[(row0 + ar0) * PADC + aq0 * 4];
    pa[1] = *(const float4*)&A[(row0 + ar1) * PADC + aq1 * 4];
    pb[0] = *(const float4*)&Bm[bk0 * PADC + col0 + cq0 * 4];
    pb[1] = *(const float4*)&Bm[bk1 * PADC + col0 + cq1 * 4];

    {
        As[0][aq0 * 4 + 0][ar0] = pa[0].x; As[0][aq0 * 4 + 1][ar0] = pa[0].y;
        As[0][aq0 * 4 + 2][ar0] = pa[0].z; As[0][aq0 * 4 + 3][ar0] = pa[0].w;
        As[0][aq1 * 4 + 0][ar1] = pa[1].x; As[0][aq1 * 4 + 1][ar1] = pa[1].y;
        As[0][aq1 * 4 + 2][ar1] = pa[1].z; As[0][aq1 * 4 + 3][ar1] = pa[1].w;
        int g0 = cq0 >> 1, w0 = cq0 & 1;
        *(float4*)&Bs[0][bk0 * BROW + g0 * 12 + w0 * 4] = pb[0];
        *(float4*)&Bs[0][bk1 * BROW + g0 * 12 + w0 * 4] = pb[1];
    }
    __syncthreads();

    const int NKT = PADC / BK;             // 13
    for (int kt = 0; kt < NKT; kt++) {
        const int buf = kt & 1;
        if (kt + 1 < NKT) {
            int k0 = (kt + 1) * BK;
            pa[0] = *(const float4*)&A[(row0 + ar0) * PADC + k0 + aq0 * 4];
            pa[1] = *(const float4*)&A[(row0 + ar1) * PADC + k0 + aq1 * 4];
            pb[0] = *(const float4*)&Bm[(k0 + bk0) * PADC + col0 + cq0 * 4];
            pb[1] = *(const float4*)&Bm[(k0 + bk1) * PADC + col0 + cq1 * 4];
        }

#pragma unroll
        for (int kk = 0; kk < BK; kk++) {
            ulonglong2 a01 = *(const ulonglong2*)&As[buf][kk][ty * 8];
            ulonglong2 a23 = *(const ulonglong2*)&As[buf][kk][ty * 8 + 4];
            const float* bg = &Bs[buf][kk * BROW + tx * 12];
            float4 b0 = *(const float4*)bg;
            {
                unsigned long long s0, s1, s2, s3;
                SPLAT2(s0, b0.x); SPLAT2(s1, b0.y); SPLAT2(s2, b0.z); SPLAT2(s3, b0.w);
                FMAF2(acc[0][0], a01.x, s0); FMAF2(acc[1][0], a01.y, s0);
                FMAF2(acc[2][0], a23.x, s0); FMAF2(acc[3][0], a23.y, s0);
                FMAF2(acc[0][1], a01.x, s1); FMAF2(acc[1][1], a01.y, s1);
                FMAF2(acc[2][1], a23.x, s1); FMAF2(acc[3][1], a23.y, s1);
                FMAF2(acc[0][2], a01.x, s2); FMAF2(acc[1][2], a01.y, s2);
                FMAF2(acc[2][2], a23.x, s2); FMAF2(acc[3][2], a23.y, s2);
                FMAF2(acc[0][3], a01.x, s3); FMAF2(acc[1][3], a01.y, s3);
                FMAF2(acc[2][3], a23.x, s3); FMAF2(acc[3][3], a23.y, s3);
            }
            float4 b1 = *(const float4*)(bg + 4);
            {
                unsigned long long s0, s1, s2, s3;
                SPLAT2(s0, b1.x); SPLAT2(s1, b1.y); SPLAT2(s2, b1.z); SPLAT2(s3, b1.w);
                FMAF2(acc[0][4], a01.x, s0); FMAF2(acc[1][4], a01.y, s0);
                FMAF2(acc[2][4], a23.x, s0); FMAF2(acc[3][4], a23.y, s0);
                FMAF2(acc[0][5], a01.x, s1); FMAF2(acc[1][5], a01.y, s1);
                FMAF2(acc[2][5], a23.x, s1); FMAF2(acc[3][5], a23.y, s1);
                FMAF2(acc[0][6], a01.x, s2); FMAF2(acc[1][6], a01.y, s2);
                FMAF2(acc[2][6], a23.x, s2); FMAF2(acc[3][6], a23.y, s2);
                FMAF2(acc[0][7], a01.x, s3); FMAF2(acc[1][7], a01.y, s3);
                FMAF2(acc[2][7], a23.x, s3); FMAF2(acc[3][7], a23.y, s3);
            }
        }

        if (kt + 1 < NKT) {
            const int nb = buf ^ 1;
            As[nb][aq0 * 4 + 0][ar0] = pa[0].x; As[nb][aq0 * 4 + 1][ar0] = pa[0].y;
            As[nb][aq0 * 4 + 2][ar0] = pa[0].z; As[nb][aq0 * 4 + 3][ar0] = pa[0].w;
            As[nb][aq1 * 4 + 0][ar1] = pa[1].x; As[nb][aq1 * 4 + 1][ar1] = pa[1].y;
            As[nb][aq1 * 4 + 2][ar1] = pa[1].z; As[nb][aq1 * 4 + 3][ar1] = pa[1].w;
            int g0 = cq0 >> 1, w0 = cq0 & 1;
            *(float4*)&Bs[nb][bk0 * BROW + g0 * 12 + w0 * 4] = pb[0];
            *(float4*)&Bs[nb][bk1 * BROW + g0 * 12 + w0 * 4] = pb[1];
            __syncthreads();
        }
    }

#pragma unroll
    for (int mp = 0; mp < 4; mp++) {
#pragma unroll
        for (int n = 0; n < 8; n++) {
            unsigned ulo, uhi;
            asm("mov.b64 {%0, %1}, %2;" : "=r"(ulo), "=r"(uhi) : "l"(acc[mp][n]));
            int gr = row0 + ty * 8 + mp * 2;
            int gc = col0 + tx * 8 + n;
            if (gc < N197) {
                if (gr < N197)     C[gr * N197 + gc]       = __uint_as_float(ulo);
                if (gr + 1 < N197) C[(gr + 1) * N197 + gc] = __uint_as_float(uhi);
            }
        }
    }
}

// ---------------------------------------------------------------------------
extern "C" void kernel_launch(void* const* d_in, const int* in_sizes, int n_in,
                              void* d_out, int out_size) {
    const float* attn = (const float*)d_in[0];  // (12,32,12,197,197) fp32
    float* out = (float*)d_out;                 // (32,197,197) fp32
    (void)in_sizes; (void)n_in; (void)out_size;

    cudaFuncSetAttribute(fused_kernel, cudaFuncAttributeMaxDynamicSharedMemorySize,
                         NN * (int)sizeof(float));

    dim3 gm(76, NLAY * NBATCH);     // 76*512 = 38912 elems, 2 per thread
    mean_kernel<<<gm, 256>>>(attn);
    fused_kernel<<<NLAY * NBATCH, NTF, NN * sizeof(float)>>>();
    dim3 gg((N197 + BN - 1) / BN, (N197 + BM - 1) / BM, NBATCH);
    gemm_kernel<<<gg, 256>>>(out);
}

// round 13
// speedup vs baseline: 1.1542x; 1.0602x over previous
#include <cuda_runtime.h>

#define N197   197
#define NN     38809        // 197*197
#define NNP    38812        // padded stride (float4-aligned)
#define NBATCH 32
#define NLAY   2            // processed layers: 4 and 11
#define KDISC  9702         // int(197*197*0.25)
#define PADR   256
#define PADC   208
#define NTF    1024

__device__ float    g_attn[NLAY * NBATCH * NNP];
__device__ float    g_norm[NLAY * NBATCH * PADR * PADC];   // zero-init; rows>=197 never written
__device__ unsigned g_hist[NLAY * NBATCH * 4096];          // zero-init; fused re-zeroes after use

// ---------------------------------------------------------------------------
// 1) mean over heads + round-0 histogram (exact R11 form — measured 24.1us)
// ---------------------------------------------------------------------------
__global__ void __launch_bounds__(256) mean_kernel(const float* __restrict__ in) {
    const int lb = blockIdx.y;           // 0..63 = li*32 + b
    const int li = lb >> 5, b = lb & 31;
    const int layer = li ? 11 : 4;
    const float* __restrict__ base = in + ((long)(layer * NBATCH + b) * 12) * NN;
    const int lane = threadIdx.x & 31;

    const int p0 = blockIdx.x * 512 + threadIdx.x;
    const int p1 = p0 + 256;
    const bool v0 = p0 < NN, v1 = p1 < NN;
    float s0 = 0.f, s1 = 0.f;
    if (v0) {
#pragma unroll
        for (int h = 0; h < 12; h++) s0 += __ldcs(&base[(long)h * NN + p0]);
    }
    if (v1) {
#pragma unroll
        for (int h = 0; h < 12; h++) s1 += __ldcs(&base[(long)h * NN + p1]);
    }
    s0 *= (1.0f / 12.0f);
    s1 *= (1.0f / 12.0f);
    if (v0) g_attn[(long)lb * NNP + p0] = s0;
    if (v1) g_attn[(long)lb * NNP + p1] = s1;

    unsigned* hb = &g_hist[lb * 4096];
    {
        unsigned key = __float_as_uint(s0) >> 20;
        unsigned m = __ballot_sync(0xffffffffu, v0);
        if (v0) {
            unsigned grp = __match_any_sync(m, key);
            if (lane == (int)__ffs(grp) - 1) atomicAdd(&hb[key], __popc(grp));
        }
    }
    {
        unsigned key = __float_as_uint(s1) >> 20;
        unsigned m = __ballot_sync(0xffffffffu, v1);
        if (v1) {
            unsigned grp = __match_any_sync(m, key);
            if (lane == (int)__ffs(grp) - 1) atomicAdd(&hb[key], __popc(grp));
        }
    }
}

// ---------------------------------------------------------------------------
// block-wide "pick the bucket containing rank"
// ---------------------------------------------------------------------------
template<int PER>
__device__ __forceinline__ void block_pick(const unsigned* cnts, int nb, int rank,
                                           unsigned* wtot, int* s_out) {
    const int t = threadIdx.x, lane = t & 31, wid = t >> 5;
    const int base = t * PER;
    unsigned h[PER];
    unsigned sum = 0;
    if (base < nb) {
#pragma unroll
        for (int j = 0; j < PER; j++) { h[j] = cnts[base + j]; sum += h[j]; }
    }
    unsigned x = sum;
#pragma unroll
    for (int o = 1; o < 32; o <<= 1) {
        unsigned y = __shfl_up_sync(0xffffffffu, x, o);
        if (lane >= o) x += y;
    }
    if (lane == 31) wtot[wid] = x;
    __syncthreads();
    if (wid == 0) {
        unsigned y = wtot[lane];
#pragma unroll
        for (int o = 1; o < 32; o <<= 1) {
            unsigned z = __shfl_up_sync(0xffffffffu, y, o);
            if (lane >= o) y += z;
        }
        wtot[lane] = y;
    }
    __syncthreads();
    unsigned excl = x - sum + (wid ? wtot[wid - 1] : 0u);
    if (base < nb && (unsigned)rank >= excl && (unsigned)rank < excl + sum) {
        unsigned c = excl; int ch = base;
#pragma unroll
        for (int j = 0; j < PER; j++) {
            if (c + h[j] > (unsigned)rank) { ch = base + j; break; }
            c += h[j];
        }
        s_out[0] = ch; s_out[1] = rank - (int)c; s_out[2] = (int)c;
    }
    __syncthreads();
}

// ---------------------------------------------------------------------------
// 2) fused: pick0 -> reg-staged load + hist1 -> pick1 -> [rare round-2/ties]
//    -> single row sweep: discard + rowsum + normalized write (R11 exact)
// ---------------------------------------------------------------------------
__global__ void __launch_bounds__(NTF) fused_kernel() {
    extern __shared__ float sm[];          // NN floats
    __shared__ unsigned hist[4096];
    __shared__ unsigned wtot[32];
    __shared__ int s_pick[3];

    const int lb = blockIdx.x;
    const int t = threadIdx.x, lane = t & 31, wid = t >> 5;

    block_pick<4>(&g_hist[lb * 4096], 4096, KDISC - 1, wtot, s_pick);
    const int B1 = s_pick[0];
    int rank = s_pick[1];

    for (int i = t; i < 4096; i += NTF) { hist[i] = 0u; g_hist[lb * 4096 + i] = 0u; }
    __syncthreads();

    // ---- register-staged load (batches of 5 float4, MLP=5/thread) + hist1 ----
    const float* src = g_attn + (long)lb * NNP;
    const float4* s4 = (const float4*)src;
    float4* d4 = (float4*)sm;
    const int N4 = NN / 4;                 // 9702
    {
        float4 v[5];
#pragma unroll
        for (int k = 0; k < 5; k++) v[k] = s4[k * NTF + t];      // max 5119 < 9702
#pragma unroll
        for (int k = 0; k < 5; k++) {
            int i = k * NTF + t;
            d4[i] = v[k];
            const float vv[4] = {v[k].x, v[k].y, v[k].z, v[k].w};
#pragma unroll
            for (int j = 0; j < 4; j++) {
                unsigned key = __float_as_uint(vv[j]);
                if ((int)(key >> 20) == B1) atomicAdd(&hist[(key >> 8) & 0xFFFu], 1u);
            }
        }
        bool ok[5];
#pragma unroll
        for (int k = 0; k < 5; k++) {
            int i = (k + 5) * NTF + t;
            ok[k] = i < N4;
            v[k] = ok[k] ? s4[i] : make_float4(0.f, 0.f, 0.f, 0.f);
        }
#pragma unroll
        for (int k = 0; k < 5; k++) {
            if (ok[k]) {
                int i = (k + 5) * NTF + t;
                d4[i] = v[k];
                const float vv[4] = {v[k].x, v[k].y, v[k].z, v[k].w};
#pragma unroll
                for (int j = 0; j < 4; j++) {
                    unsigned key = __float_as_uint(vv[j]);
                    if ((int)(key >> 20) == B1) atomicAdd(&hist[(key >> 8) & 0xFFFu], 1u);
                }
            }
        }
    }
    if (t == 0) {                          // tail element 38808
        float v = src[NN - 1]; sm[NN - 1] = v;
        unsigned key = __float_as_uint(v);
        if ((int)(key >> 20) == B1) atomicAdd(&hist[(key >> 8) & 0xFFFu], 1u);
    }
    __syncthreads();

    block_pick<4>(hist, 4096, rank, wtot, s_pick);
    const int B2 = s_pick[0];
    rank = s_pick[1];
    const unsigned K24 = ((unsigned)B1 << 12) | (unsigned)B2;
    const unsigned ties2 = hist[B2];

    int mode;           // 0: zero key24<=K24 | 1: zero key<=T | 2: zero key<T (ties pre-zeroed)
    unsigned T = 0;
    if (ties2 == 1u) {
        mode = 0;
    } else {
        for (int i = t; i < 256; i += NTF) hist[i] = 0u;
        __syncthreads();
        const int IT = (NN + NTF - 1) / NTF;   // 38
        for (int k = 0; k < IT; k++) {
            int i = k * NTF + t;
            if (i < NN) {
                unsigned key = __float_as_uint(sm[i]);
                if ((key >> 8) == K24) atomicAdd(&hist[key & 0xFFu], 1u);
            }
        }
        __syncthreads();
        block_pick<1>(hist, 256, rank, wtot, s_pick);
        const int B3 = s_pick[0];
        const int rank3 = s_pick[1];
        T = (K24 << 8) | (unsigned)B3;
        const unsigned ties3 = hist[B3];
        const int need = rank3 + 1;
        if ((unsigned)need == ties3) {
            mode = 1;
        } else {
            mode = 2;
            const int SEG = (NN + NTF - 1) / NTF;
            int start = t * SEG, end = min(start + SEG, NN);
            int cnt = 0;
            for (int i = start; i < end; i++)
                if (__float_as_uint(sm[i]) == T) cnt++;
            int x = cnt;
#pragma unroll
            for (int o = 1; o < 32; o <<= 1) {
                int y = __shfl_up_sync(0xffffffffu, x, o);
                if (lane >= o) x += y;
            }
            if (lane == 31) wtot[wid] = (unsigned)x;
            __syncthreads();
            if (wid == 0) {
                unsigned y = wtot[lane];
#pragma unroll
                for (int o = 1; o < 32; o <<= 1) {
                    unsigned z = __shfl_up_sync(0xffffffffu, y, o);
                    if (lane >= o) y += z;
                }
                wtot[lane] = y;
            }
            __syncthreads();
            int pre = x - cnt + (wid ? (int)wtot[wid - 1] : 0);
            for (int i = start; i < end; i++) {
                if (__float_as_uint(sm[i]) == T) {
                    if (pre < need && i != 0) sm[i] = 0.f;
                    pre++;
                }
            }
            __syncthreads();
        }
    }

    // ---- single sweep: discard + row sum + normalized write (warp per row) ----
    for (int r = wid; r < N197; r += 32) {
        const int rowbase = r * N197;
        float s = 0.f;
        for (int c = lane; c < N197; c += 32) {
            int i = rowbase + c;
            float v = sm[i];
            unsigned key = __float_as_uint(v);
            bool z = (mode == 0) ? ((key >> 8) <= K24)
                   : (mode == 1) ? (key <= T)
                                 : (key < T);
            if (z && i != 0) { sm[i] = 0.f; v = 0.f; }
            s += v;
        }
#pragma unroll
        for (int o = 16; o; o >>= 1) s += __shfl_xor_sync(0xffffffffu, s, o);
        const float inv = 1.0f / (s + 1.0f);   // the *0.5 cancels: (x+d)/(sum+1)

        float4* orow = (float4*)(g_norm + (long)lb * (PADR * PADC) + r * PADC);
        for (int v4 = lane; v4 < PADC / 4; v4 += 32) {   // 52 float4 per row
            int c0 = v4 * 4;
            float4 val;
            val.x = (c0     < N197) ? (sm[rowbase + c0    ] + (r == c0     ? 1.f : 0.f)) * inv : 0.f;
            val.y = (c0 + 1 < N197) ? (sm[rowbase + c0 + 1] + (r == c0 + 1 ? 1.f : 0.f)) * inv : 0.f;
            val.z = (c0 + 2 < N197) ? (sm[rowbase + c0 + 2] + (r == c0 + 2 ? 1.f : 0.f)) * inv : 0.f;
            val.w = (c0 + 3 < N197) ? (sm[rowbase + c0 + 3] + (r == c0 + 3 ? 1.f : 0.f)) * inv : 0.f;
            orow[v4] = val;
        }
    }
}

// ---------------------------------------------------------------------------
// 3) out[b] = A11[b] @ A4[b] via mma.sync m16n8k8 tf32 (legacy HMMA path).
//    128x128 tile, 4 warps, warp tile 64x64 (4x8 mma tiles). cvt.rna on load.
// ---------------------------------------------------------------------------
__device__ __forceinline__ unsigned to_tf32(float x) {
    unsigned u;
    asm("cvt.rna.tf32.f32 %0, %1;" : "=r"(u) : "f"(x));
    return u;
}

#define GBK 32
__global__ void __launch_bounds__(128) gemm_kernel(float* __restrict__ Cout) {
    __shared__ unsigned As[128][GBK + 1];   // tf32 bits, [m][k]
    __shared__ unsigned Bs[GBK][128 + 1];   // tf32 bits, [k][n]

    const int t = threadIdx.x, lane = t & 31, wid = t >> 5;
    const int b = blockIdx.z;
    const int row0 = blockIdx.y * 128, col0 = blockIdx.x * 128;
    const float* __restrict__ Ag = g_norm + (long)(NBATCH + b) * (PADR * PADC); // layer 11 [m][k]
    const float* __restrict__ Bg = g_norm + (long)b * (PADR * PADC);            // layer 4  [k][n]
    float* C = Cout + (long)b * NN;

    const int g  = lane >> 2;          // groupID (0..7)
    const int tg = lane & 3;           // threadID_in_group (0..3)
    const int wm = (wid & 1) * 64;     // warp m-offset
    const int wn = (wid >> 1) * 64;    // warp n-offset

    float acc[4][8][4];
#pragma unroll
    for (int mt = 0; mt < 4; mt++)
#pragma unroll
        for (int nt = 0; nt < 8; nt++)
#pragma unroll
            for (int j = 0; j < 4; j++) acc[mt][nt][j] = 0.f;

    for (int kc = 0; kc < 7; kc++) {
        const int k0 = kc * GBK;
        // A tile: 128 rows x 32 k (1024 float4 / 128 threads = 8 each)
#pragma unroll
        for (int l = 0; l < 8; l++) {
            int idx = l * 128 + t;
            int r = idx >> 3, q = idx & 7;
            float4 v = make_float4(0.f, 0.f, 0.f, 0.f);
            if (k0 + q * 4 < PADC)
                v = *(const float4*)&Ag[(row0 + r) * PADC + k0 + q * 4];
            As[r][q * 4 + 0] = to_tf32(v.x);
            As[r][q * 4 + 1] = to_tf32(v.y);
            As[r][q * 4 + 2] = to_tf32(v.z);
            As[r][q * 4 + 3] = to_tf32(v.w);
        }
        // B tile: 32 k-rows x 128 n (1024 float4 / 128 threads = 8 each)
        // cols >= PADC within a row read in-slot garbage that only feeds
        // never-stored output columns; k-rows are guarded (zero pad).
#pragma unroll
        for (int l = 0; l < 8; l++) {
            int idx = l * 128 + t;
            int kk = idx >> 5, nq = idx & 31;
            float4 v = make_float4(0.f, 0.f, 0.f, 0.f);
            if (k0 + kk < PADC)
                v = *(const float4*)&Bg[(k0 + kk) * PADC + col0 + nq * 4];
            Bs[kk][nq * 4 + 0] = to_tf32(v.x);
            Bs[kk][nq * 4 + 1] = to_tf32(v.y);
            Bs[kk][nq * 4 + 2] = to_tf32(v.z);
            Bs[kk][nq * 4 + 3] = to_tf32(v.w);
        }
        __syncthreads();

        const int nks = (kc == 6) ? 2 : 4;     // chunk 6: k 192..207 only
        for (int ks = 0; ks < nks; ks++) {
            const int kb = ks * 8;
            unsigned af[4][4], bf[8][2];
#pragma unroll
            for (int mt = 0; mt < 4; mt++) {
                int m = wm + mt * 16;
                af[mt][0] = As[m + g    ][kb + tg    ];
                af[mt][1] = As[m + g + 8][kb + tg    ];
                af[mt][2] = As[m + g    ][kb + tg + 4];
                af[mt][3] = As[m + g + 8][kb + tg + 4];
            }
#pragma unroll
            for (int nt = 0; nt < 8; nt++) {
                int n = wn + nt * 8 + g;
                bf[nt][0] = Bs[kb + tg    ][n];
                bf[nt][1] = Bs[kb + tg + 4][n];
            }
#pragma unroll
            for (int mt = 0; mt < 4; mt++)
#pragma unroll
                for (int nt = 0; nt < 8; nt++) {
                    asm volatile(
                        "mma.sync.aligned.m16n8k8.row.col.f32.tf32.tf32.f32 "
                        "{%0,%1,%2,%3}, {%4,%5,%6,%7}, {%8,%9}, {%0,%1,%2,%3};"
                        : "+f"(acc[mt][nt][0]), "+f"(acc[mt][nt][1]),
                          "+f"(acc[mt][nt][2]), "+f"(acc[mt][nt][3])
                        : "r"(af[mt][0]), "r"(af[mt][1]), "r"(af[mt][2]), "r"(af[mt][3]),
                          "r"(bf[nt][0]), "r"(bf[nt][1]));
                }
        }
        __syncthreads();
    }

    // epilogue: c0,c1 at (row g, cols 2tg,2tg+1); c2,c3 at row g+8
#pragma unroll
    for (int mt = 0; mt < 4; mt++) {
#pragma unroll
        for (int nt = 0; nt < 8; nt++) {
            int gr = row0 + wm + mt * 16 + g;
            int gc = col0 + wn + nt * 8 + tg * 2;
            if (gr < N197) {
                if (gc     < N197) C[gr * N197 + gc    ] = acc[mt][nt][0];
                if (gc + 1 < N197) C[gr * N197 + gc + 1] = acc[mt][nt][1];
            }
            if (gr + 8 < N197) {
                if (gc     < N197) C[(gr + 8) * N197 + gc    ] = acc[mt][nt][2];
                if (gc + 1 < N197) C[(gr + 8) * N197 + gc + 1] = acc[mt][nt][3];
            }
        }
    }
}

// ---------------------------------------------------------------------------
extern "C" void kernel_launch(void* const* d_in, const int* in_sizes, int n_in,
                              void* d_out, int out_size) {
    const float* attn = (const float*)d_in[0];  // (12,32,12,197,197) fp32
    float* out = (float*)d_out;                 // (32,197,197) fp32
    (void)in_sizes; (void)n_in; (void)out_size;

    cudaFuncSetAttribute(fused_kernel, cudaFuncAttributeMaxDynamicSharedMemorySize,
                         NN * (int)sizeof(float));

    dim3 gm(76, NLAY * NBATCH);     // 76*512 = 38912 elems, 2 per thread
    mean_kernel<<<gm, 256>>>(attn);
    fused_kernel<<<NLAY * NBATCH, NTF, NN * sizeof(float)>>>();
    dim3 gg(2, 2, NBATCH);          // 2 N-tiles x 2 M-tiles x 32 batches
    gemm_kernel<<<gg, 128>>>(out);
}